// round 15
// baseline (speedup 1.0000x reference)
#include <cuda_runtime.h>
#include <cuda_fp16.h>
#include <cstdint>
#include <cstddef>

// ---------------- problem dims ----------------
#define HD    512
#define BATCH 1024
#define TSEQ  512
#define PLEN  96
#define DIN   32

// ---------------- tiling ----------------
#define NCTA 128
#define MT   8
#define NTL  16
#define BMR  128
#define KC   64

#define A_ELE (BMR*KC)      // 8192 halfs per k64 sub-chunk
#define A_BYT (A_ELE*2)     // 16384
#define B_HI  (96*KC)       // 6144 halfs
#define B_BYT (B_HI*2)      // 12288
// job buffer: up to 2 sub-chunks: [A0|A1][B0|B1]
#define BUF_BYTES (2*A_BYT + 2*B_BYT)   // 57344
#define NSTAGE 3
#define SM_TOTAL  (NSTAGE*BUF_BYTES)    // 172032

#define WSCALE 1024.f
#define INVWS  (1.f/1024.f)

// ---------------- device globals ----------------
__device__ float g_h1[2][BATCH*HD];
__device__ float g_h2[2][BATCH*HD];
__device__ __align__(16) __half g_h1h[2][MT][8][A_ELE];
__device__ __align__(16) __half g_h2h[2][MT][8][A_ELE];
__device__ __align__(16) __half g_xh[TSEQ][MT][A_ELE];
__device__ __align__(16) __half g_w[6][NTL][8][B_HI];   // 0:e0hh 1:e1ih 2:e1hh 3:d0hh 4:d1ih 5:d1hh
__device__ __align__(16) __half g_wx[NTL][B_HI];
__device__ float g_br[4][HD], g_bz[4][HD], g_bin[4][HD], g_bhn[4][HD];
__device__ float g_y[BATCH];
__device__ unsigned g_cnt, g_gen;
__device__ unsigned g_ph[8];

// ---------------- tile addressing ----------------
__host__ __device__ __forceinline__ int offel(int r, int k) {
    return r * 64 + ((((k >> 3) ^ (r & 7)) << 3) | (k & 7));
}

// ---------------- PTX helpers ----------------
__device__ __forceinline__ uint32_t smem_u32(const void* p) {
    uint32_t a;
    asm("{ .reg .u64 t; cvta.to.shared.u64 t, %1; cvt.u32.u64 %0, t; }" : "=r"(a) : "l"(p));
    return a;
}
#define LDSM4(r, addr) asm volatile("ldmatrix.sync.aligned.m8n8.x4.shared.b16 {%0,%1,%2,%3},[%4];" \
    : "=r"((r)[0]), "=r"((r)[1]), "=r"((r)[2]), "=r"((r)[3]) : "r"(addr))
#define MMAH(d, a, b0, b1) asm volatile( \
    "mma.sync.aligned.m16n8k16.row.col.f32.f16.f16.f32 {%0,%1,%2,%3},{%4,%5,%6,%7},{%8,%9},{%0,%1,%2,%3};" \
    : "+f"((d)[0]), "+f"((d)[1]), "+f"((d)[2]), "+f"((d)[3]) \
    : "r"((a)[0]), "r"((a)[1]), "r"((a)[2]), "r"((a)[3]), "r"(b0), "r"(b1))
#define CPA16(sa, gp) asm volatile("cp.async.cg.shared.global [%0],[%1],16;" :: "r"(sa), "l"(gp))
#define CPCOMMIT()    asm volatile("cp.async.commit_group;" ::: "memory")
#define CPWAIT1()     asm volatile("cp.async.wait_group 1;" ::: "memory")
#define CPWAIT0()     asm volatile("cp.async.wait_group 0;" ::: "memory")

// ---------------- init kernels ----------------
__global__ void init_weights(
    const float* __restrict__ eWih0,
    const float* __restrict__ eWhh0, const float* __restrict__ eWih1, const float* __restrict__ eWhh1,
    const float* __restrict__ dWhh0, const float* __restrict__ dWih1, const float* __restrict__ dWhh1,
    const float* __restrict__ ebih0, const float* __restrict__ ebhh0,
    const float* __restrict__ ebih1, const float* __restrict__ ebhh1,
    const float* __restrict__ dbih0, const float* __restrict__ dbhh0,
    const float* __restrict__ dbih1, const float* __restrict__ dbhh1)
{
    const float* Wsrc[6] = {eWhh0, eWih1, eWhh1, dWhh0, dWih1, dWhh1};
    const long stride = (long)gridDim.x * blockDim.x;
    const long i0 = (long)blockIdx.x * blockDim.x + threadIdx.x;

    const long totW = 6L * NTL * 8 * 96 * KC;
    for (long i = i0; i < totW; i += stride) {
        int k = (int)(i % KC); long q = i / KC;
        int r = (int)(q % 96); q /= 96;
        int ch = (int)(q % 8); q /= 8;
        int nt = (int)(q % NTL); int ty = (int)(q / NTL);
        int g = r >> 5, jl = r & 31, j = nt * 32 + jl, kg = ch * KC + k;
        float v = Wsrc[ty][(size_t)(g * HD + j) * HD + kg] * WSCALE;
        g_w[ty][nt][ch][offel(r, k)] = __float2half(v);
    }
    const long totX = (long)NTL * 96 * KC;
    for (long i = i0; i < totX; i += stride) {
        int k = (int)(i % KC); long q = i / KC;
        int r = (int)(q % 96);   int nt = (int)(q / 96);
        int g = r >> 5, jl = r & 31, j = nt * 32 + jl;
        float v = (k < 32) ? eWih0[(size_t)(g * HD + j) * DIN + k] * WSCALE : 0.f;
        g_wx[nt][offel(r, k)] = __float2half(v);
    }
    const float* bi[4] = {ebih0, ebih1, dbih0, dbih1};
    const float* bh[4] = {ebhh0, ebhh1, dbhh0, dbhh1};
    for (long i = i0; i < 4 * HD; i += stride) {
        int tt = (int)(i / HD), j = (int)(i % HD);
        g_br[tt][j]  = bi[tt][j] + bh[tt][j];
        g_bz[tt][j]  = bi[tt][HD + j] + bh[tt][HD + j];
        g_bin[tt][j] = bi[tt][2 * HD + j];
        g_bhn[tt][j] = bh[tt][2 * HD + j];
    }
}

__global__ void init_x(const float* __restrict__ x)
{
    const long stride = (long)gridDim.x * blockDim.x;
    const long tot = (long)TSEQ * MT * BMR * KC;
    for (long i = (long)blockIdx.x * blockDim.x + threadIdx.x; i < tot; i += stride) {
        int k = (int)(i % KC); long q = i / KC;
        int r = (int)(q % BMR); q /= BMR;
        int mt = (int)(q % MT); int t = (int)(q / MT);
        __half val = __float2half(0.f);
        if (k < 32) {
            int b = mt * BMR + r;
            val = __float2half(x[((long)b * TSEQ + t) * DIN + k]);
        }
        g_xh[t][mt][offel(r, k)] = val;
    }
}

// ---------------- barriers ----------------
__device__ __forceinline__ void gbar()
{
    __syncthreads();
    if (threadIdx.x == 0) {
        __threadfence();
        unsigned gen = *(volatile unsigned*)&g_gen;
        unsigned t = atomicAdd(&g_cnt, 1u);
        if (t == NCTA - 1) {
            *(volatile unsigned*)&g_cnt = 0;
            __threadfence();
            *(volatile unsigned*)&g_gen = gen + 1;
        } else {
            while (*(volatile unsigned*)&g_gen == gen) __nanosleep(32);
        }
        __threadfence();
    }
    __syncthreads();
}
__device__ __forceinline__ void arriveph(int ph)
{
    __syncthreads();
    if (threadIdx.x == 0) { __threadfence(); atomicAdd(&g_ph[ph & 7], 1u); }
}
__device__ __forceinline__ void waitph(int ph)
{
    __syncthreads();
    if (threadIdx.x == 0) {
        const unsigned target = ((unsigned)(ph >> 3) + 1u) * NCTA;
        while (*(volatile unsigned*)&g_ph[ph & 7] < target) __nanosleep(32);
        __threadfence();
    }
    __syncthreads();
}

// ---------------- chunk compute (one k64 sub-chunk) ----------------
template<int MODE>
__device__ __forceinline__ void compute_chunk(
    uint32_t sA, uint32_t sB, int lane, int wm, int wn,
    float (&aR)[2][2][4], float (&aZ)[2][2][4],
    float (&aNH)[2][2][4], float (&aNI)[2][2][4])
{
    const int a_row = wm * 32 + (lane & 7) + ((lane >> 3) & 1) * 8;
    const int a_kh  = (lane >> 4) * 8;
    const int b_roff = (lane & 7) + ((lane >> 4) & 1) * 8;
    const int b_kh   = ((lane >> 3) & 1) * 8;

#pragma unroll
    for (int kq = 0; kq < 4; kq++) {
        const int kb = kq * 16;
        uint32_t ahi[2][4];
#pragma unroll
        for (int mtl = 0; mtl < 2; mtl++)
            LDSM4(ahi[mtl], sA + 2u * (uint32_t)offel(a_row + mtl * 16, kb + a_kh));
#pragma unroll
        for (int g = 0; g < 3; g++) {
            uint32_t bhi[4];
            LDSM4(bhi, sB + 2u * (uint32_t)offel(g * 32 + wn * 16 + b_roff, kb + b_kh));
#pragma unroll
            for (int mtl = 0; mtl < 2; mtl++)
#pragma unroll
                for (int n8 = 0; n8 < 2; n8++) {
                    float* dst = (g == 0) ? aR[mtl][n8]
                               : (g == 1) ? aZ[mtl][n8]
                               : (MODE == 0 ? aNH[mtl][n8] : aNI[mtl][n8]);
                    MMAH(dst, ahi[mtl], bhi[2 * n8], bhi[2 * n8 + 1]);
                }
        }
    }
}

// job = up to 2 consecutive k64 sub-chunks (contiguous in global memory)
struct Job { const __half* A; const __half* B; int nh; int mode; };

// ---------------- persistent kernel ----------------
__global__ void __launch_bounds__(256, 1) gru_tc(
    const float* __restrict__ dWih0,
    const float* __restrict__ outW, const float* __restrict__ outb,
    const float* __restrict__ dstart, float* __restrict__ out)
{
    extern __shared__ char smem[];
    const int tid = threadIdx.x, wid = tid >> 5, lane = tid & 31;
    const int wm = wid & 3, wn = wid >> 2;
    const int mt = blockIdx.x >> 4, nt = blockIdx.x & 15;

    // ---- per-launch state init ----
    {
        const long gs = (long)NCTA * 256;
        for (long i = (long)blockIdx.x * 256 + tid; i < (long)BATCH * HD; i += gs) {
            g_h1[0][i] = 0.f; g_h2[0][i] = 0.f;
        }
        uint32_t* z1 = (uint32_t*)&g_h1h[0][0][0][0];
        uint32_t* z2 = (uint32_t*)&g_h2h[0][0][0][0];
        const long nz = (long)MT * 8 * A_ELE / 2;
        for (long i = (long)blockIdx.x * 256 + tid; i < nz; i += gs) { z1[i] = 0; z2[i] = 0; }
        for (long i = (long)blockIdx.x * 256 + tid; i < BATCH; i += gs) g_y[i] = dstart[0];
        if (blockIdx.x == 0 && tid < 8) g_ph[tid] = 0;
    }
    gbar();

    float aR[2][2][4], aZ[2][2][4], aNH[2][2][4], aNI[2][2][4];

    auto zero_acc = [&]() {
#pragma unroll
        for (int a = 0; a < 2; a++)
#pragma unroll
            for (int b = 0; b < 2; b++)
#pragma unroll
                for (int c = 0; c < 4; c++) {
                    aR[a][b][c] = 0.f; aZ[a][b][c] = 0.f;
                    aNH[a][b][c] = 0.f; aNI[a][b][c] = 0.f;
                }
    };

    auto load_job = [&](int buf, const Job& j) {
        uint32_t dst = smem_u32(smem) + buf * BUF_BYTES;
        const char* A = (const char*)j.A;
        const char* B = (const char*)j.B;
        const int nA = j.nh * 4;                 // nh * A_BYT/16/256
        for (int i = 0; i < nA; i++)
            CPA16(dst + (tid + i * 256) * 16, A + (size_t)(tid + i * 256) * 16);
        const uint32_t bdst = dst + 2 * A_BYT;
        const int nB = j.nh * 3;
        for (int i = 0; i < nB; i++)
            CPA16(bdst + (tid + i * 256) * 16, B + (size_t)(tid + i * 256) * 16);
        CPCOMMIT();
    };

    auto compute_job = [&](int buf, const Job& j) {
        const uint32_t sbuf = smem_u32(smem) + buf * BUF_BYTES;
        for (int h = 0; h < j.nh; h++) {
            const uint32_t sA = sbuf + h * A_BYT;
            const uint32_t sB = sbuf + 2 * A_BYT + h * B_BYT;
            if (j.mode == 0) compute_chunk<0>(sA, sB, lane, wm, wn, aR, aZ, aNH, aNI);
            else             compute_chunk<1>(sA, sB, lane, wm, wn, aR, aZ, aNH, aNI);
        }
    };

    auto load2 = [&](const Job* js) { load_job(0, js[0]); load_job(1, js[1]); };

    // segment with buffers 0,1 already loading
    auto run_seg_pre = [&](const Job* js, int n) {
        int buf = 0;
        for (int i = 0; i < n; i++) {
            if (i + 1 < n) CPWAIT1(); else CPWAIT0();
            __syncthreads();
            if (i + 2 < n) load_job((buf + 2) % NSTAGE, js[i + 2]);
            compute_job(buf, js[i]);
            buf = (buf + 1) % NSTAGE;
        }
        __syncthreads();
    };

    // merged layer-1: 4 hidden double-jobs + 4 input double-jobs.
    // waitph(phA) issued exactly before the first input job's load (i+2 == 4).
    auto run_l1 = [&](const Job* js, int phA) {
        int buf = 0;
        for (int i = 0; i < 8; i++) {
            if (i + 1 < 8) CPWAIT1(); else CPWAIT0();
            __syncthreads();
            if (i + 2 < 8) {
                if (i + 2 == 4) waitph(phA);
                load_job((buf + 2) % NSTAGE, js[i + 2]);
            }
            compute_job(buf, js[i]);
            buf = (buf + 1) % NSTAGE;
        }
        __syncthreads();
    };

    auto epilogue = [&](int bt, const float* hprev, float* hout,
                        __half* hq, const float* dec0W) {
        const int qr = lane >> 2, qc = lane & 3;
        const int kbase = (nt & 1) * 32;
#pragma unroll
        for (int mtl = 0; mtl < 2; mtl++) {
#pragma unroll
            for (int fr = 0; fr < 2; fr++) {
                const int rloc = wm * 32 + mtl * 16 + qr + fr * 8;
                const int grow = mt * 128 + rloc;
                const float yy = dec0W ? __ldcg(&g_y[grow]) : 0.f;
#pragma unroll
                for (int n8 = 0; n8 < 2; n8++) {
#pragma unroll
                    for (int e = 0; e < 2; e++) {
                        const int jl = wn * 16 + n8 * 8 + qc * 2 + e;
                        const int j = nt * 32 + jl;
                        const int ci = fr * 2 + e;
                        float rv = aR[mtl][n8][ci] * INVWS;
                        float zv = aZ[mtl][n8][ci] * INVWS;
                        float nh = aNH[mtl][n8][ci] * INVWS;
                        float ni;
                        if (dec0W) {
                            rv += yy * dec0W[j];
                            zv += yy * dec0W[HD + j];
                            ni  = yy * dec0W[2 * HD + j];
                        } else {
                            ni = aNI[mtl][n8][ci] * INVWS;
                        }
                        const float r = 1.f / (1.f + __expf(-(rv + g_br[bt][j])));
                        const float z = 1.f / (1.f + __expf(-(zv + g_bz[bt][j])));
                        const float n = tanhf(ni + g_bin[bt][j] + r * (nh + g_bhn[bt][j]));
                        const float hp = hprev[(size_t)grow * HD + j];
                        const float hv = n + z * (hp - n);
                        hout[(size_t)grow * HD + j] = hv;
                        hq[offel(rloc, kbase + jl)] = __float2half(hv);
                    }
                }
            }
        }
    };

    // job-list builders
    Job jL0[5], jL1[8];
    auto buildL0enc = [&](int t, int par, Job* o) {
        for (int c = 0; c < 4; c++)
            o[c] = { &g_h1h[par][mt][2 * c][0], &g_w[0][nt][2 * c][0], 2, 0 };
        o[4] = { &g_xh[t][mt][0], &g_wx[nt][0], 1, 1 };
    };
    auto buildL0dec = [&](int par, Job* o) {
        for (int c = 0; c < 4; c++)
            o[c] = { &g_h1h[par][mt][2 * c][0], &g_w[3][nt][2 * c][0], 2, 0 };
    };

    int p = 0, st = 0;

    buildL0enc(0, 0, jL0);
    load2(jL0);

    // ---------------- encoder: 512 steps ----------------
    for (int t = 0; t < TSEQ; t++) {
        zero_acc();
        run_seg_pre(jL0, 5);                       // reads h1h[p], xh[t]
        if (st > 0) waitph(2 * st - 1);            // h2h[p] ready
        for (int c = 0; c < 4; c++) {
            jL1[c]     = { &g_h2h[p][mt][2 * c][0], &g_w[2][nt][2 * c][0], 2, 0 };
            jL1[4 + c] = { &g_h1h[1 - p][mt][2 * c][0], &g_w[1][nt][2 * c][0], 2, 1 };
        }
        load2(jL1);                                // l1-hidden prefetch
        epilogue(0, g_h1[p], g_h1[1 - p], &g_h1h[1 - p][mt][nt >> 1][0], nullptr);
        arriveph(2 * st);                          // h1 ready
        zero_acc();
        run_l1(jL1, 2 * st);
        if (t + 1 < TSEQ) buildL0enc(t + 1, 1 - p, jL0);
        else              buildL0dec(1 - p, jL0);
        load2(jL0);                                // next l0 prefetch (post wait(a))
        epilogue(1, g_h2[p], g_h2[1 - p], &g_h2h[1 - p][mt][nt >> 1][0], nullptr);
        arriveph(2 * st + 1);                      // h2 ready
        p ^= 1; st++;
    }

    // ---------------- decoder: 96 steps ----------------
    for (int s = 0; s < PLEN; s++) {
        zero_acc();
        run_seg_pre(jL0, 4);                       // reads h1h[p]
        waitph(2 * st - 1);                        // g_y + h2h[p] ready
        for (int c = 0; c < 4; c++) {
            jL1[c]     = { &g_h2h[p][mt][2 * c][0], &g_w[5][nt][2 * c][0], 2, 0 };
            jL1[4 + c] = { &g_h1h[1 - p][mt][2 * c][0], &g_w[4][nt][2 * c][0], 2, 1 };
        }
        load2(jL1);
        epilogue(2, g_h1[p], g_h1[1 - p], &g_h1h[1 - p][mt][nt >> 1][0], dWih0);
        arriveph(2 * st);
        zero_acc();
        run_l1(jL1, 2 * st);
        if (s + 1 < PLEN) { buildL0dec(1 - p, jL0); load2(jL0); }
        epilogue(3, g_h2[p], g_h2[1 - p], &g_h2h[1 - p][mt][nt >> 1][0], nullptr);
        gbar();                                    // projection reads fp32 h2 cross-CTA
        {
            const int row = blockIdx.x * 8 + wid;
            const float* hr = g_h2[1 - p] + (size_t)row * HD;
            float ss = 0.f;
#pragma unroll
            for (int q = 0; q < HD / 32; q++)
                ss += __ldcg(&hr[lane + 32 * q]) * outW[lane + 32 * q];
#pragma unroll
            for (int o = 16; o > 0; o >>= 1)
                ss += __shfl_xor_sync(0xffffffffu, ss, o);
            if (lane == 0) {
                const float v = ss + outb[0];
                g_y[row] = v;
                out[(size_t)row * PLEN + s] = v;
            }
        }
        arriveph(2 * st + 1);                      // g_y + h2h ready
        p ^= 1; st++;
    }
}

// ---------------------------------------------------------------------------
extern "C" void kernel_launch(void* const* d_in, const int* in_sizes, int n_in,
                              void* d_out, int out_size)
{
    const float* x      = (const float*)d_in[0];
    const float* eWih0  = (const float*)d_in[1];
    const float* eWhh0  = (const float*)d_in[2];
    const float* ebih0  = (const float*)d_in[3];
    const float* ebhh0  = (const float*)d_in[4];
    const float* eWih1  = (const float*)d_in[5];
    const float* eWhh1  = (const float*)d_in[6];
    const float* ebih1  = (const float*)d_in[7];
    const float* ebhh1  = (const float*)d_in[8];
    const float* dWih0  = (const float*)d_in[9];
    const float* dWhh0  = (const float*)d_in[10];
    const float* dbih0  = (const float*)d_in[11];
    const float* dbhh0  = (const float*)d_in[12];
    const float* dWih1  = (const float*)d_in[13];
    const float* dWhh1  = (const float*)d_in[14];
    const float* dbih1  = (const float*)d_in[15];
    const float* dbhh1  = (const float*)d_in[16];
    const float* outW   = (const float*)d_in[17];
    const float* outb   = (const float*)d_in[18];
    const float* dstart = (const float*)d_in[19];
    float* out = (float*)d_out;

    cudaFuncSetAttribute(gru_tc, cudaFuncAttributeMaxDynamicSharedMemorySize, SM_TOTAL);

    init_weights<<<1024, 256>>>(eWih0,
                                eWhh0, eWih1, eWhh1, dWhh0, dWih1, dWhh1,
                                ebih0, ebhh0, ebih1, ebhh1,
                                dbih0, dbhh0, dbih1, dbhh1);
    init_x<<<2048, 256>>>(x);
    gru_tc<<<NCTA, 256, SM_TOTAL>>>(dWih0, outW, outb, dstart, out);
}

// round 16
// speedup vs baseline: 1.1137x; 1.1137x over previous
#include <cuda_runtime.h>
#include <cuda_fp16.h>
#include <cstdint>
#include <cstddef>

// ---------------- problem dims ----------------
#define HD    512
#define BATCH 1024
#define TSEQ  512
#define PLEN  96
#define DIN   32

// ---------------- tiling: 256 CTAs (2/SM), 64-row m-tiles ----------------
#define NCTA 256
#define MT   8            // 128-row image tiles (storage layout unchanged)
#define NTL  16
#define BMR  64           // batch rows per CTA
#define KC   64

#define AIMG_ELE (128*KC)     // stored image sub-chunk (128 rows)
#define A_TB  (BMR*KC*2)      // 8192 bytes loaded per chunk (64 rows)
#define B_HI  (96*KC)         // 6144 halfs
#define B_BYT (B_HI*2)        // 12288
#define BUF_BYTES (A_TB + B_BYT)     // 20480
#define NSTAGE 3
#define SM_TOTAL  (NSTAGE*BUF_BYTES) // 61440

#define WSCALE 1024.f
#define INVWS  (1.f/1024.f)

// ---------------- device globals ----------------
__device__ float g_h1[2][BATCH*HD];
__device__ float g_h2[2][BATCH*HD];
__device__ __align__(16) __half g_h1h[2][MT][8][AIMG_ELE];
__device__ __align__(16) __half g_h2h[2][MT][8][AIMG_ELE];
__device__ __align__(16) __half g_xh[TSEQ][MT][AIMG_ELE];
__device__ __align__(16) __half g_w[6][NTL][8][B_HI];   // 0:e0hh 1:e1ih 2:e1hh 3:d0hh 4:d1ih 5:d1hh
__device__ __align__(16) __half g_wx[NTL][B_HI];
__device__ float g_br[4][HD], g_bz[4][HD], g_bin[4][HD], g_bhn[4][HD];
__device__ float g_y[BATCH];
__device__ unsigned g_cnt, g_gen;
__device__ unsigned g_ph[8];

// ---------------- tile addressing ----------------
__host__ __device__ __forceinline__ int offel(int r, int k) {
    return r * 64 + ((((k >> 3) ^ (r & 7)) << 3) | (k & 7));
}

// ---------------- PTX helpers ----------------
__device__ __forceinline__ uint32_t smem_u32(const void* p) {
    uint32_t a;
    asm("{ .reg .u64 t; cvta.to.shared.u64 t, %1; cvt.u32.u64 %0, t; }" : "=r"(a) : "l"(p));
    return a;
}
#define LDSM4(r, addr) asm volatile("ldmatrix.sync.aligned.m8n8.x4.shared.b16 {%0,%1,%2,%3},[%4];" \
    : "=r"((r)[0]), "=r"((r)[1]), "=r"((r)[2]), "=r"((r)[3]) : "r"(addr))
#define LDSM2(r, addr) asm volatile("ldmatrix.sync.aligned.m8n8.x2.shared.b16 {%0,%1},[%2];" \
    : "=r"((r)[0]), "=r"((r)[1]) : "r"(addr))
#define MMAH(d, a, b0, b1) asm volatile( \
    "mma.sync.aligned.m16n8k16.row.col.f32.f16.f16.f32 {%0,%1,%2,%3},{%4,%5,%6,%7},{%8,%9},{%0,%1,%2,%3};" \
    : "+f"((d)[0]), "+f"((d)[1]), "+f"((d)[2]), "+f"((d)[3]) \
    : "r"((a)[0]), "r"((a)[1]), "r"((a)[2]), "r"((a)[3]), "r"(b0), "r"(b1))
#define CPA16(sa, gp) asm volatile("cp.async.cg.shared.global [%0],[%1],16;" :: "r"(sa), "l"(gp))
#define CPCOMMIT()    asm volatile("cp.async.commit_group;" ::: "memory")
#define CPWAIT1()     asm volatile("cp.async.wait_group 1;" ::: "memory")
#define CPWAIT0()     asm volatile("cp.async.wait_group 0;" ::: "memory")

// ---------------- init kernels ----------------
__global__ void init_weights(
    const float* __restrict__ eWih0,
    const float* __restrict__ eWhh0, const float* __restrict__ eWih1, const float* __restrict__ eWhh1,
    const float* __restrict__ dWhh0, const float* __restrict__ dWih1, const float* __restrict__ dWhh1,
    const float* __restrict__ ebih0, const float* __restrict__ ebhh0,
    const float* __restrict__ ebih1, const float* __restrict__ ebhh1,
    const float* __restrict__ dbih0, const float* __restrict__ dbhh0,
    const float* __restrict__ dbih1, const float* __restrict__ dbhh1)
{
    const float* Wsrc[6] = {eWhh0, eWih1, eWhh1, dWhh0, dWih1, dWhh1};
    const long stride = (long)gridDim.x * blockDim.x;
    const long i0 = (long)blockIdx.x * blockDim.x + threadIdx.x;

    const long totW = 6L * NTL * 8 * 96 * KC;
    for (long i = i0; i < totW; i += stride) {
        int k = (int)(i % KC); long q = i / KC;
        int r = (int)(q % 96); q /= 96;
        int ch = (int)(q % 8); q /= 8;
        int nt = (int)(q % NTL); int ty = (int)(q / NTL);
        int g = r >> 5, jl = r & 31, j = nt * 32 + jl, kg = ch * KC + k;
        float v = Wsrc[ty][(size_t)(g * HD + j) * HD + kg] * WSCALE;
        g_w[ty][nt][ch][offel(r, k)] = __float2half(v);
    }
    const long totX = (long)NTL * 96 * KC;
    for (long i = i0; i < totX; i += stride) {
        int k = (int)(i % KC); long q = i / KC;
        int r = (int)(q % 96);   int nt = (int)(q / 96);
        int g = r >> 5, jl = r & 31, j = nt * 32 + jl;
        float v = (k < 32) ? eWih0[(size_t)(g * HD + j) * DIN + k] * WSCALE : 0.f;
        g_wx[nt][offel(r, k)] = __float2half(v);
    }
    const float* bi[4] = {ebih0, ebih1, dbih0, dbih1};
    const float* bh[4] = {ebhh0, ebhh1, dbhh0, dbhh1};
    for (long i = i0; i < 4 * HD; i += stride) {
        int tt = (int)(i / HD), j = (int)(i % HD);
        g_br[tt][j]  = bi[tt][j] + bh[tt][j];
        g_bz[tt][j]  = bi[tt][HD + j] + bh[tt][HD + j];
        g_bin[tt][j] = bi[tt][2 * HD + j];
        g_bhn[tt][j] = bh[tt][2 * HD + j];
    }
}

__global__ void init_x(const float* __restrict__ x)
{
    const long stride = (long)gridDim.x * blockDim.x;
    const long tot = (long)TSEQ * MT * 128 * KC;
    for (long i = (long)blockIdx.x * blockDim.x + threadIdx.x; i < tot; i += stride) {
        int k = (int)(i % KC); long q = i / KC;
        int r = (int)(q % 128); q /= 128;
        int mt = (int)(q % MT); int t = (int)(q / MT);
        __half val = __float2half(0.f);
        if (k < 32) {
            int b = mt * 128 + r;
            val = __float2half(x[((long)b * TSEQ + t) * DIN + k]);
        }
        g_xh[t][mt][offel(r, k)] = val;
    }
}

// ---------------- barriers ----------------
__device__ __forceinline__ void gbar()
{
    __syncthreads();
    if (threadIdx.x == 0) {
        __threadfence();
        unsigned gen = *(volatile unsigned*)&g_gen;
        unsigned t = atomicAdd(&g_cnt, 1u);
        if (t == NCTA - 1) {
            *(volatile unsigned*)&g_cnt = 0;
            __threadfence();
            *(volatile unsigned*)&g_gen = gen + 1;
        } else {
            while (*(volatile unsigned*)&g_gen == gen) __nanosleep(32);
        }
        __threadfence();
    }
    __syncthreads();
}
__device__ __forceinline__ void arriveph(int ph)
{
    __syncthreads();
    if (threadIdx.x == 0) { __threadfence(); atomicAdd(&g_ph[ph & 7], 1u); }
}
__device__ __forceinline__ void waitph(int ph)
{
    __syncthreads();
    if (threadIdx.x == 0) {
        const unsigned target = ((unsigned)(ph >> 3) + 1u) * NCTA;
        while (*(volatile unsigned*)&g_ph[ph & 7] < target) __nanosleep(32);
        __threadfence();
    }
    __syncthreads();
}

// ---------------- chunk compute: 64 rows, 2m x 4n warps ----------------
// Warp (wm 0-1, wn 0-3): rows [wm*32,+32), cols = 3 gates x [wn*8,+8).
template<int MODE>
__device__ __forceinline__ void compute_chunk(
    uint32_t sbuf, int lane, int wm, int wn,
    float (&aR)[2][4], float (&aZ)[2][4],
    float (&aNH)[2][4], float (&aNI)[2][4])
{
    const uint32_t sA = sbuf;
    const uint32_t sB = sbuf + A_TB;
    const int a_row = wm * 32 + (lane & 7) + ((lane >> 3) & 1) * 8;
    const int a_kh  = (lane >> 4) * 8;
    const int b_row = (lane & 7);
    const int b_kh  = ((lane >> 3) & 1) * 8;

#pragma unroll
    for (int kq = 0; kq < 4; kq++) {
        const int kb = kq * 16;
        uint32_t ahi[2][4];
#pragma unroll
        for (int mtl = 0; mtl < 2; mtl++)
            LDSM4(ahi[mtl], sA + 2u * (uint32_t)offel(a_row + mtl * 16, kb + a_kh));
#pragma unroll
        for (int g = 0; g < 3; g++) {
            uint32_t bhi[2];
            LDSM2(bhi, sB + 2u * (uint32_t)offel(g * 32 + wn * 8 + b_row, kb + b_kh));
#pragma unroll
            for (int mtl = 0; mtl < 2; mtl++) {
                float* dst = (g == 0) ? aR[mtl]
                           : (g == 1) ? aZ[mtl]
                           : (MODE == 0 ? aNH[mtl] : aNI[mtl]);
                MMAH(dst, ahi[mtl], bhi[0], bhi[1]);
            }
        }
    }
}

struct Ck { const __half* A; const __half* B; int mode; };

// ---------------- persistent kernel ----------------
__global__ void __launch_bounds__(256, 2) gru_tc(
    const float* __restrict__ dWih0,
    const float* __restrict__ outW, const float* __restrict__ outb,
    const float* __restrict__ dstart, float* __restrict__ out)
{
    extern __shared__ char smem[];
    const int tid = threadIdx.x, wid = tid >> 5, lane = tid & 31;
    const int wm = wid & 1, wn = wid >> 1;
    const int mt = blockIdx.x >> 4, nt = blockIdx.x & 15;
    const int mtim = mt >> 1;                 // 128-row image index
    const int moff = (mt & 1) * (64 * KC);    // element offset of this CTA's 64 rows

    // ---- per-launch state init ----
    {
        const long gs = (long)NCTA * 256;
        for (long i = (long)blockIdx.x * 256 + tid; i < (long)BATCH * HD; i += gs) {
            g_h1[0][i] = 0.f; g_h2[0][i] = 0.f;
        }
        uint32_t* z1 = (uint32_t*)&g_h1h[0][0][0][0];
        uint32_t* z2 = (uint32_t*)&g_h2h[0][0][0][0];
        const long nz = (long)MT * 8 * AIMG_ELE / 2;
        for (long i = (long)blockIdx.x * 256 + tid; i < nz; i += gs) { z1[i] = 0; z2[i] = 0; }
        for (long i = (long)blockIdx.x * 256 + tid; i < BATCH; i += gs) g_y[i] = dstart[0];
        if (blockIdx.x == 0 && tid < 8) g_ph[tid] = 0;
    }
    gbar();

    float aR[2][4], aZ[2][4], aNH[2][4], aNI[2][4];

    auto zero_acc = [&]() {
#pragma unroll
        for (int a = 0; a < 2; a++)
#pragma unroll
            for (int c = 0; c < 4; c++) {
                aR[a][c] = 0.f; aZ[a][c] = 0.f;
                aNH[a][c] = 0.f; aNI[a][c] = 0.f;
            }
    };

    auto load_chunk = [&](int buf, const Ck& c) {
        uint32_t dst = smem_u32(smem) + buf * BUF_BYTES;
        const char* A = (const char*)c.A;
        const char* B = (const char*)c.B;
#pragma unroll
        for (int i = 0; i < 2; i++)                    // 8 KB A
            CPA16(dst + (tid + i * 256) * 16, A + (size_t)(tid + i * 256) * 16);
        const uint32_t bdst = dst + A_TB;
#pragma unroll
        for (int i = 0; i < 3; i++)                    // 12 KB B
            CPA16(bdst + (tid + i * 256) * 16, B + (size_t)(tid + i * 256) * 16);
        CPCOMMIT();
    };

    auto load2 = [&](const Ck* cks) { load_chunk(0, cks[0]); load_chunk(1, cks[1]); };

    auto run_seg_pre = [&](const Ck* cks, int n) {
        int buf = 0;
        for (int i = 0; i < n; i++) {
            if (i + 1 < n) CPWAIT1(); else CPWAIT0();
            __syncthreads();
            if (i + 2 < n) load_chunk((buf + 2) % NSTAGE, cks[i + 2]);
            const uint32_t sbuf = smem_u32(smem) + buf * BUF_BYTES;
            if (cks[i].mode == 0) compute_chunk<0>(sbuf, lane, wm, wn, aR, aZ, aNH, aNI);
            else                  compute_chunk<1>(sbuf, lane, wm, wn, aR, aZ, aNH, aNI);
            buf = (buf + 1) % NSTAGE;
        }
        __syncthreads();
    };

    auto run_l1 = [&](const Ck* cka, const Ck* ckb, int phA) {
        int buf = 0;
        for (int i = 0; i < 16; i++) {
            if (i + 1 < 16) CPWAIT1(); else CPWAIT0();
            __syncthreads();
            if (i + 2 < 16) {
                if (i + 2 == 8) waitph(phA);
                const Ck& c = (i + 2 < 8) ? cka[i + 2] : ckb[i - 6];
                load_chunk((buf + 2) % NSTAGE, c);
            }
            const uint32_t sbuf = smem_u32(smem) + buf * BUF_BYTES;
            if (i < 8) compute_chunk<0>(sbuf, lane, wm, wn, aR, aZ, aNH, aNI);
            else       compute_chunk<1>(sbuf, lane, wm, wn, aR, aZ, aNH, aNI);
            buf = (buf + 1) % NSTAGE;
        }
        __syncthreads();
    };

    auto epilogue = [&](int bt, const float* hprev, float* hout,
                        __half* hq, const float* dec0W) {
        const int qr = lane >> 2, qc = lane & 3;
        const int kbase = (nt & 1) * 32;
#pragma unroll
        for (int mtl = 0; mtl < 2; mtl++) {
#pragma unroll
            for (int fr = 0; fr < 2; fr++) {
                const int rloc = wm * 32 + mtl * 16 + qr + fr * 8;   // 0..63
                const int grow = mt * 64 + rloc;
                const float yy = dec0W ? __ldcg(&g_y[grow]) : 0.f;
#pragma unroll
                for (int e = 0; e < 2; e++) {
                    const int jl = wn * 8 + qc * 2 + e;
                    const int j = nt * 32 + jl;
                    const int ci = fr * 2 + e;
                    float rv = aR[mtl][ci] * INVWS;
                    float zv = aZ[mtl][ci] * INVWS;
                    float nh = aNH[mtl][ci] * INVWS;
                    float ni;
                    if (dec0W) {
                        rv += yy * dec0W[j];
                        zv += yy * dec0W[HD + j];
                        ni  = yy * dec0W[2 * HD + j];
                    } else {
                        ni = aNI[mtl][ci] * INVWS;
                    }
                    const float r = 1.f / (1.f + __expf(-(rv + g_br[bt][j])));
                    const float z = 1.f / (1.f + __expf(-(zv + g_bz[bt][j])));
                    const float n = tanhf(ni + g_bin[bt][j] + r * (nh + g_bhn[bt][j]));
                    const float hp = hprev[(size_t)grow * HD + j];
                    const float hv = n + z * (hp - n);
                    hout[(size_t)grow * HD + j] = hv;
                    hq[offel((mt & 1) * 64 + rloc, kbase + jl)] = __float2half(hv);
                }
            }
        }
    };

    // chunk-list builders (A pointers offset into the 128-row images)
    Ck ckL0[9], ckA[8], ckB[8];
    auto buildL0enc = [&](int t, int par, Ck* o) {
        for (int c = 0; c < 8; c++)
            o[c] = { &g_h1h[par][mtim][c][moff], &g_w[0][nt][c][0], 0 };
        o[8] = { &g_xh[t][mtim][moff], &g_wx[nt][0], 1 };
    };
    auto buildL0dec = [&](int par, Ck* o) {
        for (int c = 0; c < 8; c++)
            o[c] = { &g_h1h[par][mtim][c][moff], &g_w[3][nt][c][0], 0 };
    };

    int p = 0, st = 0;

    buildL0enc(0, 0, ckL0);
    load2(ckL0);

    // ---------------- encoder: 512 steps ----------------
    for (int t = 0; t < TSEQ; t++) {
        zero_acc();
        run_seg_pre(ckL0, 9);
        if (st > 0) waitph(2 * st - 1);
        for (int c = 0; c < 8; c++) {
            ckA[c] = { &g_h2h[p][mtim][c][moff], &g_w[2][nt][c][0], 0 };
            ckB[c] = { &g_h1h[1 - p][mtim][c][moff], &g_w[1][nt][c][0], 1 };
        }
        load2(ckA);
        epilogue(0, g_h1[p], g_h1[1 - p], &g_h1h[1 - p][mtim][nt >> 1][0], nullptr);
        arriveph(2 * st);
        zero_acc();
        run_l1(ckA, ckB, 2 * st);
        if (t + 1 < TSEQ) buildL0enc(t + 1, 1 - p, ckL0);
        else              buildL0dec(1 - p, ckL0);
        load2(ckL0);
        epilogue(1, g_h2[p], g_h2[1 - p], &g_h2h[1 - p][mtim][nt >> 1][0], nullptr);
        arriveph(2 * st + 1);
        p ^= 1; st++;
    }

    // ---------------- decoder: 96 steps ----------------
    for (int s = 0; s < PLEN; s++) {
        zero_acc();
        run_seg_pre(ckL0, 8);
        waitph(2 * st - 1);
        for (int c = 0; c < 8; c++) {
            ckA[c] = { &g_h2h[p][mtim][c][moff], &g_w[5][nt][c][0], 0 };
            ckB[c] = { &g_h1h[1 - p][mtim][c][moff], &g_w[4][nt][c][0], 1 };
        }
        load2(ckA);
        epilogue(2, g_h1[p], g_h1[1 - p], &g_h1h[1 - p][mtim][nt >> 1][0], dWih0);
        arriveph(2 * st);
        zero_acc();
        run_l1(ckA, ckB, 2 * st);
        if (s + 1 < PLEN) { buildL0dec(1 - p, ckL0); load2(ckL0); }
        epilogue(3, g_h2[p], g_h2[1 - p], &g_h2h[1 - p][mtim][nt >> 1][0], nullptr);
        gbar();                                    // projection reads fp32 h2 cross-CTA
        if (wid < 4) {
            const int row = blockIdx.x * 4 + wid;
            const float* hr = g_h2[1 - p] + (size_t)row * HD;
            float ss = 0.f;
#pragma unroll
            for (int q = 0; q < HD / 32; q++)
                ss += __ldcg(&hr[lane + 32 * q]) * outW[lane + 32 * q];
#pragma unroll
            for (int o = 16; o > 0; o >>= 1)
                ss += __shfl_xor_sync(0xffffffffu, ss, o);
            if (lane == 0) {
                const float v = ss + outb[0];
                g_y[row] = v;
                out[(size_t)row * PLEN + s] = v;
            }
        }
        arriveph(2 * st + 1);
        p ^= 1; st++;
    }
}

// ---------------------------------------------------------------------------
extern "C" void kernel_launch(void* const* d_in, const int* in_sizes, int n_in,
                              void* d_out, int out_size)
{
    const float* x      = (const float*)d_in[0];
    const float* eWih0  = (const float*)d_in[1];
    const float* eWhh0  = (const float*)d_in[2];
    const float* ebih0  = (const float*)d_in[3];
    const float* ebhh0  = (const float*)d_in[4];
    const float* eWih1  = (const float*)d_in[5];
    const float* eWhh1  = (const float*)d_in[6];
    const float* ebih1  = (const float*)d_in[7];
    const float* ebhh1  = (const float*)d_in[8];
    const float* dWih0  = (const float*)d_in[9];
    const float* dWhh0  = (const float*)d_in[10];
    const float* dbih0  = (const float*)d_in[11];
    const float* dbhh0  = (const float*)d_in[12];
    const float* dWih1  = (const float*)d_in[13];
    const float* dWhh1  = (const float*)d_in[14];
    const float* dbih1  = (const float*)d_in[15];
    const float* dbhh1  = (const float*)d_in[16];
    const float* outW   = (const float*)d_in[17];
    const float* outb   = (const float*)d_in[18];
    const float* dstart = (const float*)d_in[19];
    float* out = (float*)d_out;

    cudaFuncSetAttribute(gru_tc, cudaFuncAttributeMaxDynamicSharedMemorySize, SM_TOTAL);

    init_weights<<<1024, 256>>>(eWih0,
                                eWhh0, eWih1, eWhh1, dWhh0, dWih1, dWhh1,
                                ebih0, ebhh0, ebih1, ebhh1,
                                dbih0, dbhh0, dbih1, dbhh1);
    init_x<<<2048, 256>>>(x);
    gru_tc<<<NCTA, 256, SM_TOTAL>>>(dWih0, outW, outb, dstart, out);
}